// round 1
// baseline (speedup 1.0000x reference)
#include <cuda_runtime.h>
#include <math.h>

#define NN   2048
#define BB   8
#define KK   8
#define HH   64
#define BN   (BB*NN)      // 16384 flattened rows
#define CAP  1280         // per-row neighbor cap for smem staging (expected ~105)
#define SEST 1284         // padded stride for se[] (conflict-free staging writes)

// ---------------- scratch (static device globals; no allocation) ----------------
__device__ __align__(16) float g_Wh [BN*512];   // multihead Wh, layout [b*n][k*64+h]
__device__ __align__(16) float g_h1 [BN*512];   // ELU(multihead attn out), concat heads
__device__ __align__(16) float g_Who[BN*HH];    // h1 @ W_o
__device__ float g_f1 [BN*KK];
__device__ float g_f2 [BN*KK];
__device__ float g_f1o[BN];
__device__ float g_f2o[BN];
__device__ int   g_cnt [NN];
__device__ int   g_cols[(size_t)NN*NN];

// ---------------- helpers ----------------
__device__ __forceinline__ float wredmax(float v) {
    #pragma unroll
    for (int o = 16; o > 0; o >>= 1) v = fmaxf(v, __shfl_xor_sync(0xFFFFFFFFu, v, o));
    return v;
}
__device__ __forceinline__ float wredsum(float v) {
    #pragma unroll
    for (int o = 16; o > 0; o >>= 1) v += __shfl_xor_sync(0xFFFFFFFFu, v, o);
    return v;
}
__device__ __forceinline__ float lrelu(float x) { return x > 0.f ? x : 0.2f * x; }
__device__ __forceinline__ float elu(float x)   { return x > 0.f ? x : expm1f(x); }

// ---------------- K0: CSR build from bias_mat (0.0 = edge, -1e9 = none) ----------------
__global__ void k0_csr(const float* __restrict__ bias) {
    __shared__ int cnt0;
    int i = blockIdx.x;
    if (threadIdx.x == 0) cnt0 = 0;
    __syncthreads();
    const float* row = bias + (size_t)i * NN;
    for (int j = threadIdx.x; j < NN; j += blockDim.x) {
        if (row[j] == 0.0f) {
            int p = atomicAdd(&cnt0, 1);
            g_cols[(size_t)i * NN + p] = j;
        }
    }
    __syncthreads();
    if (threadIdx.x == 0) g_cnt[i] = cnt0;
}

// ---------------- K1: Wh = concat(inputs,envs,state) @ Wcat  ([16384x96]@[96x512]) ----------------
// block: 64 rows x 256 cols, thread tile 8x8, K staged in 6 chunks of 16.
__global__ void __launch_bounds__(256) k1_gemm(const float* __restrict__ inp,
                                               const float* __restrict__ env,
                                               const float* __restrict__ st,
                                               const float* __restrict__ Wh_w) {
    __shared__ float Asm[64][96];
    __shared__ __align__(16) float Bsm[16][256];
    int tid  = threadIdx.x;
    int row0 = blockIdx.y * 64;
    int col0 = blockIdx.x * 256;

    for (int l = tid; l < 64 * 96; l += 256) {
        int r = l / 96, d = l % 96;
        int g = row0 + r;
        float v;
        if (d < 2)       v = inp[g * 2 + d];
        else if (d < 32) v = env[g * 30 + (d - 2)];
        else             v = st [g * 64 + (d - 32)];
        Asm[r][d] = v;
    }

    float acc[8][8];
    #pragma unroll
    for (int u = 0; u < 8; u++)
        #pragma unroll
        for (int v = 0; v < 8; v++) acc[u][v] = 0.f;

    int cr = tid & 31, rr = tid >> 5;
    int c0 = cr * 8, r0 = rr * 8;

    for (int kc = 0; kc < 6; kc++) {
        __syncthreads();
        for (int l = tid; l < 16 * 256; l += 256) {
            int dd = l >> 8, c = l & 255;
            int gc = col0 + c, d = kc * 16 + dd;
            // Wcat[d][gc] = W_h[head=gc>>6][d][gc&63]
            Bsm[dd][c] = Wh_w[(gc >> 6) * (96 * 64) + d * 64 + (gc & 63)];
        }
        __syncthreads();
        #pragma unroll
        for (int dd = 0; dd < 16; dd++) {
            float a[8];
            #pragma unroll
            for (int u = 0; u < 8; u++) a[u] = Asm[r0 + u][kc * 16 + dd];
            float4 b0 = *(const float4*)&Bsm[dd][c0];
            float4 b1 = *(const float4*)&Bsm[dd][c0 + 4];
            float bb[8] = {b0.x, b0.y, b0.z, b0.w, b1.x, b1.y, b1.z, b1.w};
            #pragma unroll
            for (int u = 0; u < 8; u++)
                #pragma unroll
                for (int v = 0; v < 8; v++) acc[u][v] += a[u] * bb[v];
        }
    }

    #pragma unroll
    for (int u = 0; u < 8; u++) {
        float* dst = g_Wh + (size_t)(row0 + r0 + u) * 512 + col0 + c0;
        *(float4*)(dst)     = make_float4(acc[u][0], acc[u][1], acc[u][2], acc[u][3]);
        *(float4*)(dst + 4) = make_float4(acc[u][4], acc[u][5], acc[u][6], acc[u][7]);
    }
}

// ---------------- Kf: f1/f2 = Wh . a1/a2 per (row, head) ----------------
__global__ void kf_h(const float* __restrict__ a1, const float* __restrict__ a2) {
    int row  = blockIdx.x;                  // 0..BN-1
    int k    = threadIdx.x >> 5;
    int lane = threadIdx.x & 31;
    float2 w  = ((const float2*)g_Wh)[(size_t)row * 256 + k * 32 + lane];
    float2 A1 = ((const float2*)a1)[k * 32 + lane];
    float2 A2 = ((const float2*)a2)[k * 32 + lane];
    float p1 = wredsum(w.x * A1.x + w.y * A1.y);
    float p2 = wredsum(w.x * A2.x + w.y * A2.y);
    if (lane == 0) { g_f1[row * 8 + k] = p1; g_f2[row * 8 + k] = p2; }
}

// ---------------- K2: multihead sparse softmax-aggregate + ELU -> h1 ----------------
// One block per (i, b); warp k owns head k. e/p staged in smem (lane-parallel exp).
__global__ void __launch_bounds__(256) k2_att() {
    __shared__ int   scols[CAP];
    __shared__ float se[KK * SEST];
    int i = blockIdx.x, b = blockIdx.y;
    int tid = threadIdx.x;
    int k = tid >> 5, lane = tid & 31;
    int row = b * NN + i;
    int cnt = g_cnt[i];
    const int* cl = g_cols + (size_t)i * NN;
    const float2* Wb = (const float2*)g_Wh + (size_t)b * NN * 256 + k * 32 + lane;

    float a0 = 0.f, a1v = 0.f, s = 0.f;

    if (cnt <= CAP) {
        for (int l = tid; l < cnt; l += 256) scols[l] = cl[l];
        __syncthreads();
        // stage e cooperatively: thread (kk, jj) covers (head, edge)
        int kk = tid & 7, jj = tid >> 3;
        float f1k = g_f1[row * 8 + kk];
        for (int j = jj; j < cnt; j += 32) {
            int c = scols[j];
            float f2v = g_f2[(b * NN + c) * 8 + kk];
            se[kk * SEST + j] = lrelu(f1k + f2v);
        }
        __syncthreads();
        // per-warp softmax over this head's staged e
        float m = -1e30f;
        for (int j = lane; j < cnt; j += 32) m = fmaxf(m, se[k * SEST + j]);
        m = wredmax(m);
        for (int j = lane; j < cnt; j += 32) {
            float p = __expf(se[k * SEST + j] - m);
            se[k * SEST + j] = p;
            s += p;
        }
        s = wredsum(s);
        __syncwarp();
        // gather/accumulate (L2-bound loop)
        #pragma unroll 4
        for (int j = 0; j < cnt; j++) {
            int   c = scols[j];
            float p = se[k * SEST + j];
            float2 v = Wb[c * 256];
            a0 += p * v.x; a1v += p * v.y;
        }
    } else {
        // fallback (never expected at 5% density): warp-uniform inline path
        float f1v = g_f1[row * 8 + k];
        float m = -1e30f;
        for (int j = lane; j < cnt; j += 32) {
            float f2v = g_f2[(b * NN + cl[j]) * 8 + k];
            m = fmaxf(m, lrelu(f1v + f2v));
        }
        m = wredmax(m);
        for (int j = 0; j < cnt; j++) {
            int c = __ldg(cl + j);
            float f2v = __ldg(g_f2 + (b * NN + c) * 8 + k);
            float p = __expf(lrelu(f1v + f2v) - m);
            s += p;
            float2 v = Wb[c * 256];
            a0 += p * v.x; a1v += p * v.y;
        }
    }

    float inv = 1.f / s;
    a0 = elu(a0 * inv);
    a1v = elu(a1v * inv);
    ((float2*)g_h1)[(size_t)row * 256 + k * 32 + lane] = make_float2(a0, a1v);
}

// ---------------- K3: Who = h1 @ W_o  ([16384x512]@[512x64]) ----------------
// block 128 threads: 64 rows x 64 cols, thread tile 8x4, K in 8 chunks of 64.
__global__ void __launch_bounds__(128) k3_gemm(const float* __restrict__ Wo) {
    __shared__ float Asm[64][65];
    __shared__ __align__(16) float Bsm[64][64];
    int tid  = threadIdx.x;
    int row0 = blockIdx.x * 64;
    int cr = tid & 15, rr = tid >> 4;
    int c0 = cr * 4, r0 = rr * 8;

    float acc[8][4];
    #pragma unroll
    for (int u = 0; u < 8; u++)
        #pragma unroll
        for (int v = 0; v < 4; v++) acc[u][v] = 0.f;

    for (int kc = 0; kc < 8; kc++) {
        __syncthreads();
        for (int l = tid; l < 64 * 64; l += 128) {
            int dd = l & 63, r = l >> 6;
            Asm[r][dd] = g_h1[(size_t)(row0 + r) * 512 + kc * 64 + dd];
        }
        for (int l = tid; l < 64 * 64; l += 128) {
            int c = l & 63, dd = l >> 6;
            Bsm[dd][c] = Wo[(kc * 64 + dd) * 64 + c];
        }
        __syncthreads();
        #pragma unroll
        for (int dd = 0; dd < 64; dd++) {
            float4 bv = *(const float4*)&Bsm[dd][c0];
            #pragma unroll
            for (int u = 0; u < 8; u++) {
                float a = Asm[r0 + u][dd];
                acc[u][0] += a * bv.x; acc[u][1] += a * bv.y;
                acc[u][2] += a * bv.z; acc[u][3] += a * bv.w;
            }
        }
    }
    #pragma unroll
    for (int u = 0; u < 8; u++)
        *(float4*)&g_Who[(size_t)(row0 + r0 + u) * 64 + c0] =
            make_float4(acc[u][0], acc[u][1], acc[u][2], acc[u][3]);
}

// ---------------- Kf_o: f1o/f2o = Who . a1o/a2o ----------------
__global__ void kf_o(const float* __restrict__ a1o, const float* __restrict__ a2o) {
    int w = threadIdx.x >> 5, lane = threadIdx.x & 31;
    int row = blockIdx.x * 8 + w;
    float2 v  = ((const float2*)g_Who)[(size_t)row * 32 + lane];
    float2 A1 = ((const float2*)a1o)[lane];
    float2 A2 = ((const float2*)a2o)[lane];
    float p1 = wredsum(v.x * A1.x + v.y * A1.y);
    float p2 = wredsum(v.x * A2.x + v.y * A2.y);
    if (lane == 0) { g_f1o[row] = p1; g_f2o[row] = p2; }
}

// ---------------- K4: single-head sparse softmax-aggregate + ELU -> out ----------------
__global__ void __launch_bounds__(256) k4_att(float* __restrict__ out) {
    int w = threadIdx.x >> 5, lane = threadIdx.x & 31;
    int i = blockIdx.x * 8 + w;
    int b = blockIdx.y;
    int cnt = g_cnt[i];
    const int* cl = g_cols + (size_t)i * NN;
    float f1v = g_f1o[b * NN + i];

    float m = -1e30f;
    for (int j = lane; j < cnt; j += 32) {
        float f2v = g_f2o[b * NN + cl[j]];
        m = fmaxf(m, lrelu(f1v + f2v));
    }
    m = wredmax(m);

    float s = 0.f, a0 = 0.f, a1v = 0.f;
    const float2* W2 = (const float2*)g_Who + (size_t)b * NN * 32 + lane;
    #pragma unroll 2
    for (int j = 0; j < cnt; j++) {
        int c = __ldg(cl + j);
        float f2v = __ldg(g_f2o + b * NN + c);
        float p = __expf(lrelu(f1v + f2v) - m);
        s += p;
        float2 v = W2[c * 32];
        a0 += p * v.x; a1v += p * v.y;
    }
    float inv = 1.f / s;
    a0 = elu(a0 * inv);
    a1v = elu(a1v * inv);
    ((float2*)out)[(size_t)(b * NN + i) * 32 + lane] = make_float2(a0, a1v);
}

// ---------------- launcher ----------------
extern "C" void kernel_launch(void* const* d_in, const int* in_sizes, int n_in,
                              void* d_out, int out_size) {
    const float* inp  = (const float*)d_in[0];
    const float* env  = (const float*)d_in[1];
    const float* st   = (const float*)d_in[2];
    const float* bias = (const float*)d_in[3];
    const float* W_h  = (const float*)d_in[4];
    const float* a1h  = (const float*)d_in[5];
    const float* a2h  = (const float*)d_in[6];
    const float* W_o  = (const float*)d_in[7];
    const float* a1o  = (const float*)d_in[8];
    const float* a2o  = (const float*)d_in[9];
    float* out = (float*)d_out;

    k0_csr <<<NN, 256>>>(bias);
    k1_gemm<<<dim3(2, BN / 64), 256>>>(inp, env, st, W_h);
    kf_h   <<<BN, 256>>>(a1h, a2h);
    k2_att <<<dim3(NN, BB), 256>>>();
    k3_gemm<<<BN / 64, 128>>>(W_o);
    kf_o   <<<BN / 8, 256>>>(a1o, a2o);
    k4_att <<<dim3(NN / 8, BB), 256>>>(out);
}

// round 2
// speedup vs baseline: 1.2237x; 1.2237x over previous
#include <cuda_runtime.h>
#include <cuda_fp16.h>
#include <math.h>

#define NN   2048
#define BB   8
#define KK   8
#define HH   64
#define BN   (BB*NN)      // 16384 flattened rows
#define CAP  192          // per-row neighbor cap (binomial mean ~103, max ~145)
#define SEST 196          // padded stride for se[]

// ---------------- scratch (static device globals; no allocation) ----------------
__device__ __align__(16) float  g_Wh  [BN*512];   // multihead Wh fp32 (for f1/f2)
__device__ __align__(16) __half g_Whh [BN*512];   // fp16 gather copy of Wh
__device__ __align__(16) float  g_h1  [BN*512];   // ELU(multihead attn out), concat heads
__device__ __align__(16) float  g_Who [BN*HH];    // h1 @ W_o (fp32, for f1o/f2o)
__device__ __align__(16) __half g_Whoh[BN*HH];    // fp16 gather copy of Who
__device__ float g_f1 [BN*KK];
__device__ float g_f2 [BN*KK];
__device__ float g_f1o[BN];
__device__ float g_f2o[BN];
__device__ int   g_cnt [NN];
__device__ int   g_cols[(size_t)NN*NN];

// ---------------- helpers ----------------
__device__ __forceinline__ float wredmax(float v) {
    #pragma unroll
    for (int o = 16; o > 0; o >>= 1) v = fmaxf(v, __shfl_xor_sync(0xFFFFFFFFu, v, o));
    return v;
}
__device__ __forceinline__ float wredsum(float v) {
    #pragma unroll
    for (int o = 16; o > 0; o >>= 1) v += __shfl_xor_sync(0xFFFFFFFFu, v, o);
    return v;
}
__device__ __forceinline__ float lrelu(float x) { return x > 0.f ? x : 0.2f * x; }
__device__ __forceinline__ float elu(float x)   { return x > 0.f ? x : expm1f(x); }

// ---------------- K0: CSR build from bias_mat (0.0 = edge, -1e9 = none) ----------------
__global__ void k0_csr(const float* __restrict__ bias) {
    __shared__ int cnt0;
    int i = blockIdx.x;
    if (threadIdx.x == 0) cnt0 = 0;
    __syncthreads();
    const float* row = bias + (size_t)i * NN;
    for (int j = threadIdx.x; j < NN; j += blockDim.x) {
        if (row[j] == 0.0f) {
            int p = atomicAdd(&cnt0, 1);
            g_cols[(size_t)i * NN + p] = j;
        }
    }
    __syncthreads();
    if (threadIdx.x == 0) g_cnt[i] = cnt0;
}

// ---------------- K1: Wh = concat(inputs,envs,state) @ Wcat  ([16384x96]@[96x512]) ----------------
__global__ void __launch_bounds__(256) k1_gemm(const float* __restrict__ inp,
                                               const float* __restrict__ env,
                                               const float* __restrict__ st,
                                               const float* __restrict__ Wh_w) {
    __shared__ float Asm[64][96];
    __shared__ __align__(16) float Bsm[16][256];
    int tid  = threadIdx.x;
    int row0 = blockIdx.y * 64;
    int col0 = blockIdx.x * 256;

    for (int l = tid; l < 64 * 96; l += 256) {
        int r = l / 96, d = l % 96;
        int g = row0 + r;
        float v;
        if (d < 2)       v = inp[g * 2 + d];
        else if (d < 32) v = env[g * 30 + (d - 2)];
        else             v = st [g * 64 + (d - 32)];
        Asm[r][d] = v;
    }

    float acc[8][8];
    #pragma unroll
    for (int u = 0; u < 8; u++)
        #pragma unroll
        for (int v = 0; v < 8; v++) acc[u][v] = 0.f;

    int cr = tid & 31, rr = tid >> 5;
    int c0 = cr * 8, r0 = rr * 8;

    for (int kc = 0; kc < 6; kc++) {
        __syncthreads();
        for (int l = tid; l < 16 * 256; l += 256) {
            int dd = l >> 8, c = l & 255;
            int gc = col0 + c, d = kc * 16 + dd;
            Bsm[dd][c] = Wh_w[(gc >> 6) * (96 * 64) + d * 64 + (gc & 63)];
        }
        __syncthreads();
        #pragma unroll
        for (int dd = 0; dd < 16; dd++) {
            float a[8];
            #pragma unroll
            for (int u = 0; u < 8; u++) a[u] = Asm[r0 + u][kc * 16 + dd];
            float4 b0 = *(const float4*)&Bsm[dd][c0];
            float4 b1 = *(const float4*)&Bsm[dd][c0 + 4];
            float bb[8] = {b0.x, b0.y, b0.z, b0.w, b1.x, b1.y, b1.z, b1.w};
            #pragma unroll
            for (int u = 0; u < 8; u++)
                #pragma unroll
                for (int v = 0; v < 8; v++) acc[u][v] += a[u] * bb[v];
        }
    }

    #pragma unroll
    for (int u = 0; u < 8; u++) {
        size_t idx = (size_t)(row0 + r0 + u) * 512 + col0 + c0;
        float* dst = g_Wh + idx;
        *(float4*)(dst)     = make_float4(acc[u][0], acc[u][1], acc[u][2], acc[u][3]);
        *(float4*)(dst + 4) = make_float4(acc[u][4], acc[u][5], acc[u][6], acc[u][7]);
        union { __half2 h[4]; uint4 u4; } pk;
        pk.h[0] = __floats2half2_rn(acc[u][0], acc[u][1]);
        pk.h[1] = __floats2half2_rn(acc[u][2], acc[u][3]);
        pk.h[2] = __floats2half2_rn(acc[u][4], acc[u][5]);
        pk.h[3] = __floats2half2_rn(acc[u][6], acc[u][7]);
        *(uint4*)(g_Whh + idx) = pk.u4;
    }
}

// ---------------- Kf: f1/f2 = Wh . a1/a2 per (row, head) ----------------
__global__ void kf_h(const float* __restrict__ a1, const float* __restrict__ a2) {
    int row  = blockIdx.x;
    int k    = threadIdx.x >> 5;
    int lane = threadIdx.x & 31;
    float2 w  = ((const float2*)g_Wh)[(size_t)row * 256 + k * 32 + lane];
    float2 A1 = ((const float2*)a1)[k * 32 + lane];
    float2 A2 = ((const float2*)a2)[k * 32 + lane];
    float p1 = wredsum(w.x * A1.x + w.y * A1.y);
    float p2 = wredsum(w.x * A2.x + w.y * A2.y);
    if (lane == 0) { g_f1[row * 8 + k] = p1; g_f2[row * 8 + k] = p2; }
}

// ---------------- K2: multihead sparse softmax-aggregate + ELU -> h1 ----------------
// One block per (i, b); warp k owns head k. fp16 gather (128B = 1 L2 line per edge-head).
__global__ void __launch_bounds__(256) k2_att() {
    __shared__ int   scols[CAP];
    __shared__ float se[KK * SEST];
    int i = blockIdx.x, b = blockIdx.y;
    int tid = threadIdx.x;
    int k = tid >> 5, lane = tid & 31;
    int row = b * NN + i;
    int cnt = g_cnt[i];
    const int* cl = g_cols + (size_t)i * NN;
    const __half2* Wb = (const __half2*)g_Whh + (size_t)b * NN * 256 + k * 32 + lane;

    float a0 = 0.f, a1v = 0.f, s = 0.f;

    if (cnt <= CAP) {
        for (int l = tid; l < cnt; l += 256) scols[l] = cl[l];
        __syncthreads();
        // stage e cooperatively: thread (kk, jj) covers (head, edge)
        int kk = tid & 7, jj = tid >> 3;
        float f1k = g_f1[row * 8 + kk];
        for (int j = jj; j < cnt; j += 32) {
            int c = scols[j];
            float f2v = g_f2[(b * NN + c) * 8 + kk];
            se[kk * SEST + j] = lrelu(f1k + f2v);
        }
        __syncthreads();
        // per-warp softmax over this head's staged e
        float m = -1e30f;
        for (int j = lane; j < cnt; j += 32) m = fmaxf(m, se[k * SEST + j]);
        m = wredmax(m);
        for (int j = lane; j < cnt; j += 32) {
            float p = __expf(se[k * SEST + j] - m);
            se[k * SEST + j] = p;
            s += p;
        }
        s = wredsum(s);
        __syncwarp();
        // gather/accumulate (L2-bound loop), 4-way ILP
        int j = 0;
        for (; j + 4 <= cnt; j += 4) {
            int c0 = scols[j], c1 = scols[j+1], c2 = scols[j+2], c3 = scols[j+3];
            float p0 = se[k*SEST+j], p1 = se[k*SEST+j+1], p2 = se[k*SEST+j+2], p3 = se[k*SEST+j+3];
            __half2 v0 = Wb[(size_t)c0 * 256];
            __half2 v1 = Wb[(size_t)c1 * 256];
            __half2 v2 = Wb[(size_t)c2 * 256];
            __half2 v3 = Wb[(size_t)c3 * 256];
            float2 f0 = __half22float2(v0), f1x = __half22float2(v1);
            float2 f2x = __half22float2(v2), f3 = __half22float2(v3);
            a0  += p0*f0.x + p1*f1x.x + p2*f2x.x + p3*f3.x;
            a1v += p0*f0.y + p1*f1x.y + p2*f2x.y + p3*f3.y;
        }
        for (; j < cnt; j++) {
            int c = scols[j];
            float p = se[k*SEST+j];
            float2 f = __half22float2(Wb[(size_t)c * 256]);
            a0 += p * f.x; a1v += p * f.y;
        }
    } else {
        // fallback (not expected at 5% density): warp-uniform inline path
        float f1v = g_f1[row * 8 + k];
        float m = -1e30f;
        for (int j = lane; j < cnt; j += 32) {
            float f2v = g_f2[(b * NN + cl[j]) * 8 + k];
            m = fmaxf(m, lrelu(f1v + f2v));
        }
        m = wredmax(m);
        for (int j = 0; j < cnt; j++) {
            int c = __ldg(cl + j);
            float f2v = __ldg(g_f2 + (b * NN + c) * 8 + k);
            float p = __expf(lrelu(f1v + f2v) - m);
            s += p;
            float2 f = __half22float2(Wb[(size_t)c * 256]);
            a0 += p * f.x; a1v += p * f.y;
        }
    }

    float inv = 1.f / s;
    a0 = elu(a0 * inv);
    a1v = elu(a1v * inv);
    ((float2*)g_h1)[(size_t)row * 256 + k * 32 + lane] = make_float2(a0, a1v);
}

// ---------------- K3: Who = h1 @ W_o  ([16384x512]@[512x64]) ----------------
__global__ void __launch_bounds__(128) k3_gemm(const float* __restrict__ Wo) {
    __shared__ float Asm[64][65];
    __shared__ __align__(16) float Bsm[64][64];
    int tid  = threadIdx.x;
    int row0 = blockIdx.x * 64;
    int cr = tid & 15, rr = tid >> 4;
    int c0 = cr * 4, r0 = rr * 8;

    float acc[8][4];
    #pragma unroll
    for (int u = 0; u < 8; u++)
        #pragma unroll
        for (int v = 0; v < 4; v++) acc[u][v] = 0.f;

    for (int kc = 0; kc < 8; kc++) {
        __syncthreads();
        for (int l = tid; l < 64 * 64; l += 128) {
            int dd = l & 63, r = l >> 6;
            Asm[r][dd] = g_h1[(size_t)(row0 + r) * 512 + kc * 64 + dd];
        }
        for (int l = tid; l < 64 * 64; l += 128) {
            int c = l & 63, dd = l >> 6;
            Bsm[dd][c] = Wo[(kc * 64 + dd) * 64 + c];
        }
        __syncthreads();
        #pragma unroll
        for (int dd = 0; dd < 64; dd++) {
            float4 bv = *(const float4*)&Bsm[dd][c0];
            #pragma unroll
            for (int u = 0; u < 8; u++) {
                float a = Asm[r0 + u][dd];
                acc[u][0] += a * bv.x; acc[u][1] += a * bv.y;
                acc[u][2] += a * bv.z; acc[u][3] += a * bv.w;
            }
        }
    }
    #pragma unroll
    for (int u = 0; u < 8; u++) {
        size_t idx = (size_t)(row0 + r0 + u) * 64 + c0;
        *(float4*)&g_Who[idx] =
            make_float4(acc[u][0], acc[u][1], acc[u][2], acc[u][3]);
        union { __half2 h[2]; uint2 u2; } pk;
        pk.h[0] = __floats2half2_rn(acc[u][0], acc[u][1]);
        pk.h[1] = __floats2half2_rn(acc[u][2], acc[u][3]);
        *(uint2*)(g_Whoh + idx) = pk.u2;
    }
}

// ---------------- Kf_o: f1o/f2o = Who . a1o/a2o ----------------
__global__ void kf_o(const float* __restrict__ a1o, const float* __restrict__ a2o) {
    int w = threadIdx.x >> 5, lane = threadIdx.x & 31;
    int row = blockIdx.x * 8 + w;
    float2 v  = ((const float2*)g_Who)[(size_t)row * 32 + lane];
    float2 A1 = ((const float2*)a1o)[lane];
    float2 A2 = ((const float2*)a2o)[lane];
    float p1 = wredsum(v.x * A1.x + v.y * A1.y);
    float p2 = wredsum(v.x * A2.x + v.y * A2.y);
    if (lane == 0) { g_f1o[row] = p1; g_f2o[row] = p2; }
}

// ---------------- K4: single-head sparse softmax-aggregate + ELU -> out ----------------
__global__ void __launch_bounds__(256) k4_att(float* __restrict__ out) {
    int w = threadIdx.x >> 5, lane = threadIdx.x & 31;
    int i = blockIdx.x * 8 + w;
    int b = blockIdx.y;
    int cnt = g_cnt[i];
    const int* cl = g_cols + (size_t)i * NN;
    float f1v = g_f1o[b * NN + i];

    float m = -1e30f;
    for (int j = lane; j < cnt; j += 32) {
        float f2v = g_f2o[b * NN + cl[j]];
        m = fmaxf(m, lrelu(f1v + f2v));
    }
    m = wredmax(m);

    float s = 0.f, a0 = 0.f, a1v = 0.f;
    const __half2* W2 = (const __half2*)g_Whoh + (size_t)b * NN * 32 + lane;
    #pragma unroll 4
    for (int j = 0; j < cnt; j++) {
        int c = __ldg(cl + j);
        float f2v = __ldg(g_f2o + b * NN + c);
        float p = __expf(lrelu(f1v + f2v) - m);
        s += p;
        float2 f = __half22float2(W2[(size_t)c * 32]);
        a0 += p * f.x; a1v += p * f.y;
    }
    float inv = 1.f / s;
    a0 = elu(a0 * inv);
    a1v = elu(a1v * inv);
    ((float2*)out)[(size_t)(b * NN + i) * 32 + lane] = make_float2(a0, a1v);
}

// ---------------- launcher ----------------
extern "C" void kernel_launch(void* const* d_in, const int* in_sizes, int n_in,
                              void* d_out, int out_size) {
    const float* inp  = (const float*)d_in[0];
    const float* env  = (const float*)d_in[1];
    const float* st   = (const float*)d_in[2];
    const float* bias = (const float*)d_in[3];
    const float* W_h  = (const float*)d_in[4];
    const float* a1h  = (const float*)d_in[5];
    const float* a2h  = (const float*)d_in[6];
    const float* W_o  = (const float*)d_in[7];
    const float* a1o  = (const float*)d_in[8];
    const float* a2o  = (const float*)d_in[9];
    float* out = (float*)d_out;

    k0_csr <<<NN, 256>>>(bias);
    k1_gemm<<<dim3(2, BN / 64), 256>>>(inp, env, st, W_h);
    kf_h   <<<BN, 256>>>(a1h, a2h);
    k2_att <<<dim3(NN, BB), 256>>>();
    k3_gemm<<<BN / 64, 128>>>(W_o);
    kf_o   <<<BN / 8, 256>>>(a1o, a2o);
    k4_att <<<dim3(NN / 8, BB), 256>>>(out);
}